// round 2
// baseline (speedup 1.0000x reference)
#include <cuda_runtime.h>
#include <math.h>

#define N_ROWS 65536
#define P_ROWS 2048
#define D_DIM  512

// Scratch for precomputed squared norms (no device allocation allowed).
__device__ float g_xsq[N_ROWS];
__device__ float g_psq[P_ROWS];

// One warp per row: sum of squares of a D=512 fp32 row.
// which == 0 -> write g_xsq, which == 1 -> write g_psq.
__global__ void row_norms_kernel(const float* __restrict__ x, int nrows, int which) {
    int warp = (blockIdx.x * blockDim.x + threadIdx.x) >> 5;
    int lane = threadIdx.x & 31;
    if (warp >= nrows) return;
    const float4* rp = reinterpret_cast<const float4*>(x + (size_t)warp * D_DIM);
    float s = 0.f;
#pragma unroll
    for (int i = 0; i < D_DIM / 4 / 32; i++) {
        float4 v = rp[lane + i * 32];
        s += v.x * v.x + v.y * v.y + v.z * v.z + v.w * v.w;
    }
#pragma unroll
    for (int o = 16; o > 0; o >>= 1) s += __shfl_xor_sync(0xffffffffu, s, o);
    if (lane == 0) {
        if (which == 0) g_xsq[warp] = s;
        else            g_psq[warp] = s;
    }
}

#define BM 128
#define BN 128
#define BK 16
#define TM 8
#define TN 8

// C[n][p] = -sqrt(max(||x_n||^2 - 2 * <x_n, p_p> + ||p_p||^2, 0))
// A = embeddings [N, D] row-major, B = prototypes [P, D] row-major (NT gemm).
__global__ __launch_bounds__(256, 2) void gemm_dist_kernel(
    const float* __restrict__ A,
    const float* __restrict__ B,
    float* __restrict__ C)
{
    __shared__ float As[BK][BM];
    __shared__ float Bs[BK][BN];

    const int tid = threadIdx.x;
    const int tm = tid >> 4;   // 0..15
    const int tn = tid & 15;   // 0..15
    const int brow = blockIdx.y * BM;
    const int bcol = blockIdx.x * BN;

    float acc[TM][TN];
#pragma unroll
    for (int i = 0; i < TM; i++)
#pragma unroll
        for (int j = 0; j < TN; j++) acc[i][j] = 0.f;

    float regM[TM], regN[TN];

    for (int k0 = 0; k0 < D_DIM; k0 += BK) {
        // Load 128x16 tiles of A and B, store transposed (k-major) into smem.
        // 512 float4 per tile, 256 threads -> 2 float4 each per matrix.
#pragma unroll
        for (int l = 0; l < 2; l++) {
            int f   = tid * 2 + l;
            int row = f >> 2;
            int kq  = (f & 3) << 2;
            float4 va = *reinterpret_cast<const float4*>(
                A + (size_t)(brow + row) * D_DIM + k0 + kq);
            As[kq + 0][row] = va.x;
            As[kq + 1][row] = va.y;
            As[kq + 2][row] = va.z;
            As[kq + 3][row] = va.w;
            float4 vb = *reinterpret_cast<const float4*>(
                B + (size_t)(bcol + row) * D_DIM + k0 + kq);
            Bs[kq + 0][row] = vb.x;
            Bs[kq + 1][row] = vb.y;
            Bs[kq + 2][row] = vb.z;
            Bs[kq + 3][row] = vb.w;
        }
        __syncthreads();

#pragma unroll
        for (int k = 0; k < BK; k++) {
#pragma unroll
            for (int i = 0; i < TM; i += 4) {
                float4 v = *reinterpret_cast<const float4*>(&As[k][tm * TM + i]);
                regM[i] = v.x; regM[i + 1] = v.y; regM[i + 2] = v.z; regM[i + 3] = v.w;
            }
#pragma unroll
            for (int j = 0; j < TN; j += 4) {
                float4 v = *reinterpret_cast<const float4*>(&Bs[k][tn * TN + j]);
                regN[j] = v.x; regN[j + 1] = v.y; regN[j + 2] = v.z; regN[j + 3] = v.w;
            }
#pragma unroll
            for (int i = 0; i < TM; i++)
#pragma unroll
                for (int j = 0; j < TN; j++)
                    acc[i][j] = fmaf(regM[i], regN[j], acc[i][j]);
        }
        __syncthreads();
    }

    // Epilogue: distances.
    float xs[TM], ps[TN];
#pragma unroll
    for (int i = 0; i < TM; i++) xs[i] = g_xsq[brow + tm * TM + i];
#pragma unroll
    for (int j = 0; j < TN; j++) ps[j] = g_psq[bcol + tn * TN + j];

#pragma unroll
    for (int i = 0; i < TM; i++) {
        float out4[TN];
#pragma unroll
        for (int j = 0; j < TN; j++) {
            float d2 = fmaxf(fmaf(-2.f, acc[i][j], xs[i] + ps[j]), 0.f);
            out4[j] = -sqrtf(d2);
        }
        float* cp = C + (size_t)(brow + tm * TM + i) * P_ROWS + bcol + tn * TN;
#pragma unroll
        for (int j = 0; j < TN; j += 4) {
            float4 v = make_float4(out4[j], out4[j + 1], out4[j + 2], out4[j + 3]);
            *reinterpret_cast<float4*>(cp + j) = v;
        }
    }
}

extern "C" void kernel_launch(void* const* d_in, const int* in_sizes, int n_in,
                              void* d_out, int out_size) {
    const float* emb   = (const float*)d_in[0];  // [N, D]
    const float* proto = (const float*)d_in[1];  // [P, D]
    float* out = (float*)d_out;                  // [N, P]

    // Norms: one warp per row, 8 warps per block.
    row_norms_kernel<<<N_ROWS / 8, 256>>>(emb, N_ROWS, 0);
    row_norms_kernel<<<P_ROWS / 8, 256>>>(proto, P_ROWS, 1);

    dim3 grid(P_ROWS / BN, N_ROWS / BM);
    gemm_dist_kernel<<<grid, 256>>>(emb, proto, out);
}

// round 4
// speedup vs baseline: 5.1514x; 5.1514x over previous
#include <cuda_runtime.h>
#include <cuda_bf16.h>
#include <stdint.h>
#include <math.h>

#define N_ROWS 65536
#define P_ROWS 2048
#define D_DIM  512

#define BM 128
#define BN 128
#define BK 32            // bf16 elements -> 64 bytes per row-chunk
#define STAGES 4
#define K_ITERS (D_DIM / BK)   // 16

// smem geometry: padded 80B row stride (conflict-free ldmatrix, 16B-aligned cp.async)
#define ROWB 80
#define TILE_BYTES (128 * ROWB)        // 10240
#define STAGE_BYTES (2 * TILE_BYTES)   // A + B = 20480
#define SMEM_TOTAL (STAGES * STAGE_BYTES)  // 81920

// ---------------- scratch (static device globals; no runtime allocation) ----
__device__ float g_xsq[N_ROWS];
__device__ float g_psq[P_ROWS];
__device__ __nv_bfloat16 g_ebf[(size_t)N_ROWS * D_DIM];
__device__ __nv_bfloat16 g_pbf[(size_t)P_ROWS * D_DIM];

// ---------------- PTX helpers ----------------------------------------------
__device__ __forceinline__ uint32_t smem_u32(const void* p) {
    uint32_t a;
    asm("{ .reg .u64 t; cvta.to.shared.u64 t, %1; cvt.u32.u64 %0, t; }" : "=r"(a) : "l"(p));
    return a;
}

#define CP_ASYNC16(dst, src) \
    asm volatile("cp.async.cg.shared.global [%0], [%1], 16;" :: "r"(dst), "l"(src) : "memory")
#define CP_COMMIT() asm volatile("cp.async.commit_group;" ::: "memory")
#define CP_WAIT(n)  asm volatile("cp.async.wait_group %0;" :: "n"(n) : "memory")

#define LDMATRIX_X4(r0, r1, r2, r3, addr) \
    asm volatile("ldmatrix.sync.aligned.m8n8.x4.shared.b16 {%0,%1,%2,%3}, [%4];" \
        : "=r"(r0), "=r"(r1), "=r"(r2), "=r"(r3) : "r"(addr))

#define MMA_16816_BF16(c0, c1, c2, c3, a0, a1, a2, a3, b0, b1) \
    asm volatile("mma.sync.aligned.m16n8k16.row.col.f32.bf16.bf16.f32 " \
        "{%0,%1,%2,%3}, {%4,%5,%6,%7}, {%8,%9}, {%0,%1,%2,%3};" \
        : "+f"(c0), "+f"(c1), "+f"(c2), "+f"(c3) \
        : "r"(a0), "r"(a1), "r"(a2), "r"(a3), "r"(b0), "r"(b1))

// ---------------- convert fp32 -> bf16 + row norms --------------------------
__device__ __forceinline__ void convert_body(const float* __restrict__ x,
                                             __nv_bfloat16* __restrict__ xb,
                                             float* __restrict__ xsq, int nrows) {
    int warp = (blockIdx.x * blockDim.x + threadIdx.x) >> 5;
    int lane = threadIdx.x & 31;
    if (warp >= nrows) return;
    const float4* rp = reinterpret_cast<const float4*>(x + (size_t)warp * D_DIM);
    uint2* wp = reinterpret_cast<uint2*>(xb + (size_t)warp * D_DIM);
    float s = 0.f;
#pragma unroll
    for (int i = 0; i < 4; i++) {
        float4 v = rp[lane + i * 32];
        s += v.x * v.x + v.y * v.y + v.z * v.z + v.w * v.w;
        __nv_bfloat162 lo = __floats2bfloat162_rn(v.x, v.y);
        __nv_bfloat162 hi = __floats2bfloat162_rn(v.z, v.w);
        uint2 u;
        u.x = *reinterpret_cast<uint32_t*>(&lo);
        u.y = *reinterpret_cast<uint32_t*>(&hi);
        wp[lane + i * 32] = u;
    }
#pragma unroll
    for (int o = 16; o > 0; o >>= 1) s += __shfl_xor_sync(0xffffffffu, s, o);
    if (lane == 0) xsq[warp] = s;
}

__global__ void convert_e_kernel(const float* __restrict__ x) {
    convert_body(x, g_ebf, g_xsq, N_ROWS);
}
__global__ void convert_p_kernel(const float* __restrict__ x) {
    convert_body(x, g_pbf, g_psq, P_ROWS);
}

// ---------------- main GEMM + distance kernel -------------------------------
__global__ __launch_bounds__(256, 2) void gemm_mma_kernel(float* __restrict__ C) {
    extern __shared__ char smem[];
    const uint32_t sb = smem_u32(smem);

    const int tid  = threadIdx.x;
    const int wid  = tid >> 5;
    const int lane = tid & 31;
    const int wm = wid >> 2;   // 0..1   (64-row slab inside CTA)
    const int wn = wid & 3;    // 0..3   (32-col slab inside CTA)

    const int bRow = blockIdx.y * BM;
    const int bCol = blockIdx.x * BN;

    const char* gA = reinterpret_cast<const char*>(g_ebf) + (size_t)bRow * (D_DIM * 2);
    const char* gB = reinterpret_cast<const char*>(g_pbf) + (size_t)bCol * (D_DIM * 2);

    // cp.async assignment: thread t loads 32B of A and 32B of B per stage.
    const int ldRow = tid >> 1;            // 0..127
    const int ldC   = (tid & 1) * 32;      // 0 or 32 (byte offset within 64B chunk)
    const size_t gOffBase = (size_t)ldRow * (D_DIM * 2) + ldC;

    // ldmatrix lane addressing: row (lane&15), 16B chunk (lane>>4)
    const int lmRow   = lane & 15;
    const int lmChunk = (lane >> 4) << 4;  // 0 or 16 bytes

    float acc[4][4][4];
#pragma unroll
    for (int i = 0; i < 4; i++)
#pragma unroll
        for (int j = 0; j < 4; j++)
#pragma unroll
            for (int q = 0; q < 4; q++) acc[i][j][q] = 0.f;

    // ---- prologue: fill STAGES-1 pipeline stages ----
#pragma unroll
    for (int s = 0; s < STAGES - 1; s++) {
        uint32_t dstA = sb + s * STAGE_BYTES + ldRow * ROWB + ldC;
        const char* srcA = gA + gOffBase + s * (BK * 2);
        CP_ASYNC16(dstA, srcA);
        CP_ASYNC16(dstA + 16, srcA + 16);
        uint32_t dstB = dstA + TILE_BYTES;
        const char* srcB = gB + gOffBase + s * (BK * 2);
        CP_ASYNC16(dstB, srcB);
        CP_ASYNC16(dstB + 16, srcB + 16);
        CP_COMMIT();
    }

    // ---- mainloop ----
    for (int k = 0; k < K_ITERS; k++) {
        CP_WAIT(STAGES - 2);
        __syncthreads();

        // issue load for stage k+STAGES-1
        {
            int kl = k + STAGES - 1;
            if (kl < K_ITERS) {
                int s = kl & (STAGES - 1);
                uint32_t dstA = sb + s * STAGE_BYTES + ldRow * ROWB + ldC;
                const char* srcA = gA + gOffBase + kl * (BK * 2);
                CP_ASYNC16(dstA, srcA);
                CP_ASYNC16(dstA + 16, srcA + 16);
                uint32_t dstB = dstA + TILE_BYTES;
                const char* srcB = gB + gOffBase + kl * (BK * 2);
                CP_ASYNC16(dstB, srcB);
                CP_ASYNC16(dstB + 16, srcB + 16);
            }
            CP_COMMIT();
        }

        const uint32_t stA = sb + (k & (STAGES - 1)) * STAGE_BYTES;
        const uint32_t stB = stA + TILE_BYTES;

#pragma unroll
        for (int kk = 0; kk < 2; kk++) {
            const int kByte = kk * 32 + lmChunk;

            uint32_t a[4][4];
#pragma unroll
            for (int i = 0; i < 4; i++) {
                uint32_t addr = stA + (wm * 64 + i * 16 + lmRow) * ROWB + kByte;
                LDMATRIX_X4(a[i][0], a[i][1], a[i][2], a[i][3], addr);
            }
            uint32_t b[2][4];
#pragma unroll
            for (int jp = 0; jp < 2; jp++) {
                uint32_t addr = stB + (wn * 32 + jp * 16 + lmRow) * ROWB + kByte;
                LDMATRIX_X4(b[jp][0], b[jp][1], b[jp][2], b[jp][3], addr);
            }
#pragma unroll
            for (int i = 0; i < 4; i++) {
#pragma unroll
                for (int j = 0; j < 4; j++) {
                    int jp = j >> 1, h = j & 1;
                    MMA_16816_BF16(acc[i][j][0], acc[i][j][1], acc[i][j][2], acc[i][j][3],
                                   a[i][0], a[i][1], a[i][2], a[i][3],
                                   b[jp][h], b[jp][2 + h]);
                }
            }
        }
    }

    // ---- epilogue: d = xs + ps - 2*cross ; out = -sqrt(max(d,0)) ----
    const int r0 = lane >> 2;        // 0..7
    const int cq = (lane & 3) * 2;   // 0,2,4,6

    float ps0[4], ps1[4];
#pragma unroll
    for (int j = 0; j < 4; j++) {
        int gc = bCol + wn * 32 + j * 8 + cq;
        ps0[j] = g_psq[gc];
        ps1[j] = g_psq[gc + 1];
    }

#pragma unroll
    for (int i = 0; i < 4; i++) {
#pragma unroll
        for (int h = 0; h < 2; h++) {
            int grow = bRow + wm * 64 + i * 16 + r0 + h * 8;
            float xs = g_xsq[grow];
            float* crow = C + (size_t)grow * P_ROWS + bCol + wn * 32;
#pragma unroll
            for (int j = 0; j < 4; j++) {
                float c0 = acc[i][j][h * 2 + 0];
                float c1 = acc[i][j][h * 2 + 1];
                float d0 = fmaf(-2.f, c0, xs + ps0[j]);
                float d1 = fmaf(-2.f, c1, xs + ps1[j]);
                float2 o;
                o.x = (d0 > 0.f) ? (-d0 * rsqrtf(d0)) : 0.f;
                o.y = (d1 > 0.f) ? (-d1 * rsqrtf(d1)) : 0.f;
                *reinterpret_cast<float2*>(crow + j * 8 + cq) = o;
            }
        }
    }
}

// ---------------- launch ----------------------------------------------------
extern "C" void kernel_launch(void* const* d_in, const int* in_sizes, int n_in,
                              void* d_out, int out_size) {
    const float* emb   = (const float*)d_in[0];  // [N, D]
    const float* proto = (const float*)d_in[1];  // [P, D]
    float* out = (float*)d_out;                  // [N, P]

    cudaFuncSetAttribute(gemm_mma_kernel,
                         cudaFuncAttributeMaxDynamicSharedMemorySize, SMEM_TOTAL);

    convert_e_kernel<<<N_ROWS / 8, 256>>>(emb);
    convert_p_kernel<<<P_ROWS / 8, 256>>>(proto);

    dim3 grid(P_ROWS / BN, N_ROWS / BM);  // (16, 512): columns fastest -> A reuse in L2
    gemm_mma_kernel<<<grid, 256, SMEM_TOTAL>>>(out);
}